// round 1
// baseline (speedup 1.0000x reference)
#include <cuda_runtime.h>
#include <math.h>

#define TSEQ   1024
#define NBATCH 64
#define HID    512
#define G3     1536
#define INFEAT 256
#define MROWS  (TSEQ * NBATCH)   // 65536

// ---------------- scratch (device globals; no allocation) ----------------
__device__ float g_xg[(size_t)MROWS * G3];   // [t*64+b][1536] gate preacts (reused layer0/1)
__device__ float g_y0[(size_t)MROWS * HID];  // [t*64+b][512]  tanh(h) of layer 0
__device__ float g_h[2][HID * NBATCH];       // k-major: [buf][k][b]
__device__ unsigned g_bar_count;             // zero-init; returns to 0 each run
__device__ unsigned g_bar_gen;               // monotonically increasing across runs (ok)

// ---------------- input projection GEMM: g_xg = A @ W + bias ----------------
// Row m -> A offset (m&63)*sB + (m>>6)*sT ; A = Aext ? Aext : g_y0
// BM=128, BN=64, BK=16, 256 threads, 8x4 per-thread tile.
__global__ void __launch_bounds__(256) proj_kernel(
    const float* __restrict__ Aext, const float* __restrict__ W,
    const float* __restrict__ bias,
    int K, long sB, long sT)
{
    const int N = G3;
    const float* A = Aext ? Aext : g_y0;

    __shared__ float As[16][132];   // [k][row], padded
    __shared__ float Bs[16][64];    // [k][col]

    int tid  = threadIdx.x;
    int row0 = blockIdx.y * 128;
    int col0 = blockIdx.x * 64;
    int tx = tid & 15, ty = tid >> 4;

    // A loader: each thread owns 1 row, 8 consecutive k's (two float4)
    int ar  = row0 + (tid >> 1);
    const float* arow = A + (long)(ar & 63) * sB + (long)(ar >> 6) * sT;
    int akc = (tid & 1) * 8;
    int r   = tid >> 1;

    // B loader
    int bkr = tid >> 4;            // 0..15
    int bc  = (tid & 15) * 4;      // 0..60
    const float* bptr = W + (long)bkr * N + col0 + bc;

    float acc[8][4];
#pragma unroll
    for (int i = 0; i < 8; ++i)
#pragma unroll
        for (int j = 0; j < 4; ++j) acc[i][j] = 0.f;

    for (int k0 = 0; k0 < K; k0 += 16) {
        float4 a0 = *(const float4*)(arow + k0 + akc);
        float4 a1 = *(const float4*)(arow + k0 + akc + 4);
        float4 bb = *(const float4*)(bptr + (long)k0 * N);

        As[akc + 0][r] = a0.x; As[akc + 1][r] = a0.y;
        As[akc + 2][r] = a0.z; As[akc + 3][r] = a0.w;
        As[akc + 4][r] = a1.x; As[akc + 5][r] = a1.y;
        As[akc + 6][r] = a1.z; As[akc + 7][r] = a1.w;
        *(float4*)&Bs[bkr][bc] = bb;
        __syncthreads();

#pragma unroll
        for (int kk = 0; kk < 16; ++kk) {
            float4 bv  = *(const float4*)&Bs[kk][tx * 4];
            float4 av0 = *(const float4*)&As[kk][ty * 8];
            float4 av1 = *(const float4*)&As[kk][ty * 8 + 4];
            float av[8] = {av0.x, av0.y, av0.z, av0.w, av1.x, av1.y, av1.z, av1.w};
#pragma unroll
            for (int i = 0; i < 8; ++i) {
                acc[i][0] = fmaf(av[i], bv.x, acc[i][0]);
                acc[i][1] = fmaf(av[i], bv.y, acc[i][1]);
                acc[i][2] = fmaf(av[i], bv.z, acc[i][2]);
                acc[i][3] = fmaf(av[i], bv.w, acc[i][3]);
            }
        }
        __syncthreads();
    }

    float4 bia = *(const float4*)(bias + col0 + tx * 4);
#pragma unroll
    for (int i = 0; i < 8; ++i) {
        long m = row0 + ty * 8 + i;
        float4 v;
        v.x = acc[i][0] + bia.x;
        v.y = acc[i][1] + bia.y;
        v.z = acc[i][2] + bia.z;
        v.w = acc[i][3] + bia.w;
        *(float4*)(g_xg + m * N + col0 + tx * 4) = v;
    }
}

// ---------------- grid barrier (tid 0 only; callers fence first) ----------------
__device__ __forceinline__ void grid_barrier_arrive_wait(unsigned target, unsigned nb)
{
    if (atomicAdd(&g_bar_count, 1u) == nb - 1u) {
        g_bar_count = 0u;
        __threadfence();
        atomicAdd(&g_bar_gen, 1u);
    } else {
        while (*((volatile unsigned*)&g_bar_gen) != target) { }
    }
}

// ---------------- persistent GRU recurrence ----------------
// grid = 128 CTAs x 256 threads. CTA (bgrp, hcgrp): batch rows [bgrp*32, +32),
// hidden cols [hcgrp*8, +8) -> 24 gate cols of W_h cached in SMEM.
// h double-buffered in global, k-major [512][64]. One grid barrier per step.
__global__ void __launch_bounds__(256, 1) gru_rec_kernel(
    const float* __restrict__ Wh, const float* __restrict__ bhn,
    int write_y, float* __restrict__ cout)
{
    const int NB = 32, NG = 24;
    extern __shared__ float sh[];
    float* ws  = sh;                 // [512][24]   49152 B
    float* hs  = ws + 512 * NG;      // [512][33]   67584 B (padded, transposed h)
    float* red = hs + 512 * 33;      // [8][32][25] 25600 B
    float* xgs = red + 8 * 32 * 25;  // [32][25]     2560 B

    int tid  = threadIdx.x;
    int warp = tid >> 5, lane = tid & 31;
    int bgrp = blockIdx.x & 1;
    int hc0  = (blockIdx.x >> 1) * 8;
    int b0   = bgrp * NB;

    // load W_h slice into SMEM (once)
    for (int f = tid; f < 512 * NG; f += 256) {
        int k = f / NG, j = f - k * NG;
        int gc = (j >> 3) * HID + hc0 + (j & 7);
        ws[f] = Wh[(long)k * G3 + gc];
    }

    unsigned lgen = 0;
    if (tid == 0) lgen = *((volatile unsigned*)&g_bar_gen);

    // elementwise mapping: cols fastest for coalesced writes
    int eci = tid & 7;        // hidden col within slice
    int eb  = tid >> 3;       // local batch row 0..31
    int ehc = hc0 + eci;

    for (int t = 0; t < TSEQ; ++t) {
        int cur = t & 1, nxt = cur ^ 1;

        // stage xg tile [32 b][24 gate cols] (two float4 per row)
        if (tid < 96) {
            int b = tid & 31, grp = tid >> 5;   // grp 0..2 = r,z,n
            const float* p = g_xg + ((long)t * NBATCH + b0 + b) * G3 + grp * HID + hc0;
            float4 v0 = ((const float4*)p)[0];
            float4 v1 = ((const float4*)p)[1];
            float* q = xgs + b * 25 + grp * 8;
            q[0] = v0.x; q[1] = v0.y; q[2] = v0.z; q[3] = v0.w;
            q[4] = v1.x; q[5] = v1.y; q[6] = v1.z; q[7] = v1.w;
        }

        // stage h (k-major global -> padded transposed SMEM); t==0: zeros
        if (t == 0) {
            for (int f = tid; f < 512 * 33; f += 256) hs[f] = 0.f;
        } else {
#pragma unroll
            for (int it = 0; it < 16; ++it) {
                int f4 = tid + it * 256;        // 0..4095
                int k = f4 >> 3, bq = f4 & 7;
                float4 v = __ldcg((const float4*)&g_h[cur][k * NBATCH + b0 + bq * 4]);
                float* q = hs + k * 33 + bq * 4;
                q[0] = v.x; q[1] = v.y; q[2] = v.z; q[3] = v.w;
            }
        }
        __syncthreads();

        // partial GEMM: warp w covers k in [w*64, w*64+64)
        float acc[NG];
#pragma unroll
        for (int j = 0; j < NG; ++j) acc[j] = 0.f;
        int kbase = warp << 6;
#pragma unroll 4
        for (int kk = 0; kk < 64; ++kk) {
            int k = kbase + kk;
            float hv = hs[k * 33 + lane];
            const float4* wp = (const float4*)(ws + k * NG);
#pragma unroll
            for (int q = 0; q < 6; ++q) {
                float4 w4 = wp[q];
                acc[4 * q + 0] = fmaf(hv, w4.x, acc[4 * q + 0]);
                acc[4 * q + 1] = fmaf(hv, w4.y, acc[4 * q + 1]);
                acc[4 * q + 2] = fmaf(hv, w4.z, acc[4 * q + 2]);
                acc[4 * q + 3] = fmaf(hv, w4.w, acc[4 * q + 3]);
            }
        }
        {
            float* rp = red + (warp * NB + lane) * 25;
#pragma unroll
            for (int j = 0; j < NG; ++j) rp[j] = acc[j];
        }
        __syncthreads();

        // reduce 8 warps + gate math; thread -> (eb, eci)
        float hr = 0.f, hz = 0.f, hnv = 0.f;
#pragma unroll
        for (int w = 0; w < 8; ++w) {
            const float* pr = red + (w * NB + eb) * 25;
            hr  += pr[eci];
            hz  += pr[8 + eci];
            hnv += pr[16 + eci];
        }
        float xr = xgs[eb * 25 + eci];
        float xz = xgs[eb * 25 + 8 + eci];
        float xn = xgs[eb * 25 + 16 + eci];
        float hprev = hs[ehc * 33 + eb];

        float rg = 1.f / (1.f + __expf(-(xr + hr)));
        float zg = 1.f / (1.f + __expf(-(xz + hz)));
        float ng = tanhf(xn + rg * (hnv + bhn[ehc]));
        float hnew = (1.f - zg) * ng + zg * hprev;

        g_h[nxt][ehc * NBATCH + b0 + eb] = hnew;
        if (write_y)
            g_y0[((long)t * NBATCH + b0 + eb) * HID + ehc] = tanhf(hnew);
        if (t == TSEQ - 1)
            cout[(b0 + eb) * HID + ehc] = hnew;

        // publish writes, then grid barrier (one per step; h is double buffered)
        __threadfence();
        __syncthreads();
        if (tid == 0) { lgen += 1u; grid_barrier_arrive_wait(lgen, 128u); }
        __syncthreads();
    }
}

// ---------------- dense head: out = tanh(tanh(c1) @ W_out + b_out) ----------------
__global__ void __launch_bounds__(512) dense_kernel(
    const float* __restrict__ Wout, const float* __restrict__ bout,
    float* __restrict__ out)
{
    __shared__ float tsh[HID];
    int b = blockIdx.x;
    int j = threadIdx.x;
    tsh[j] = tanhf(g_h[0][j * NBATCH + b]);   // final h of layer 1 (k-major)
    __syncthreads();
    float s = bout[j];
#pragma unroll 8
    for (int k = 0; k < HID; ++k)
        s = fmaf(tsh[k], Wout[(long)k * 512 + j], s);
    out[b * 512 + j] = tanhf(s);
}

// ---------------- launch ----------------
extern "C" void kernel_launch(void* const* d_in, const int* in_sizes, int n_in,
                              void* d_out, int out_size)
{
    const float* x     = (const float*)d_in[0];
    const float* W_i0  = (const float*)d_in[1];
    const float* b_i0  = (const float*)d_in[2];
    const float* W_h0  = (const float*)d_in[3];
    const float* b_hn0 = (const float*)d_in[4];
    const float* W_i1  = (const float*)d_in[5];
    const float* b_i1  = (const float*)d_in[6];
    const float* W_h1  = (const float*)d_in[7];
    const float* b_hn1 = (const float*)d_in[8];
    const float* W_out = (const float*)d_in[9];
    const float* b_out = (const float*)d_in[10];

    float* out = (float*)d_out;
    float* c0  = out + 64 * 512;
    float* c1  = out + 2 * 64 * 512;

    size_t rec_smem = (size_t)(512 * 24 + 512 * 33 + 8 * 32 * 25 + 32 * 25) * sizeof(float);
    cudaFuncSetAttribute(gru_rec_kernel,
                         cudaFuncAttributeMaxDynamicSharedMemorySize, (int)rec_smem);

    dim3 pgrid(G3 / 64, MROWS / 128);

    // layer 0
    proj_kernel<<<pgrid, 256>>>(x, W_i0, b_i0, INFEAT, (long)1024 * 256, (long)256);
    gru_rec_kernel<<<128, 256, rec_smem>>>(W_h0, b_hn0, 1, c0);
    // layer 1
    proj_kernel<<<pgrid, 256>>>(nullptr, W_i1, b_i1, HID, (long)512, (long)64 * 512);
    gru_rec_kernel<<<128, 256, rec_smem>>>(W_h1, b_hn1, 0, c1);
    // head
    dense_kernel<<<64, 512>>>(W_out, b_out, out);
}

// round 3
// speedup vs baseline: 1.4996x; 1.4996x over previous
#include <cuda_runtime.h>
#include <math.h>

#define TSEQ   1024
#define NBATCH 64
#define HID    512
#define G3     1536
#define INFEAT 256
#define MROWS  (TSEQ * NBATCH)   // 65536

// packed f32x2 FMA: d.lo = a.lo*b.lo + c.lo ; d.hi = a.hi*b.hi + c.hi
#define FMA2(d, a, b, c) \
    asm("fma.rn.f32x2 %0, %1, %2, %3;" : "=l"(d) : "l"(a), "l"(b), "l"(c))

__device__ __forceinline__ float2 u2f2(unsigned long long u) {
    float2 f;
    asm("mov.b64 {%0, %1}, %2;" : "=f"(f.x), "=f"(f.y) : "l"(u));
    return f;
}

// ---------------- scratch (device globals; no allocation) ----------------
__device__ float g_xg[(size_t)MROWS * G3];   // [t*64+b][1536] gate preacts
__device__ float g_y0[(size_t)MROWS * HID];  // [t*64+b][512]  tanh(h) of layer 0
__device__ float g_h[2][HID * NBATCH];       // k-major: [buf][k][b]
__device__ unsigned g_bar_count;
__device__ unsigned g_bar_gen;

// ---------------- input projection GEMM: g_xg = A @ W + bias ----------------
// BM=128, BN=64, BK=16, 256 threads, 8x4 per-thread tile, FFMA2 inner product.
__global__ void __launch_bounds__(256) proj_kernel(
    const float* __restrict__ Aext, const float* __restrict__ W,
    const float* __restrict__ bias,
    int K, long sB, long sT)
{
    const int N = G3;
    const float* A = Aext ? Aext : g_y0;

    __shared__ __align__(16) float As2[16][260];  // duplicated pairs: [k][2*row]
    __shared__ __align__(16) float Bs[16][64];    // [k][col]

    int tid  = threadIdx.x;
    int row0 = blockIdx.y * 128;
    int col0 = blockIdx.x * 64;
    int tx = tid & 15, ty = tid >> 4;

    // A loader: thread owns row r = tid>>1, 8 consecutive k's (two float4), dup-store
    int ar  = row0 + (tid >> 1);
    const float* arow = A + (long)(ar & 63) * sB + (long)(ar >> 6) * sT;
    int akc = (tid & 1) * 8;
    int r2  = (tid >> 1) * 2;

    // B loader
    int bkr = tid >> 4;            // 0..15
    int bc  = (tid & 15) * 4;      // 0..60
    const float* bptr = W + (long)bkr * N + col0 + bc;

    unsigned long long acc[8][2];
#pragma unroll
    for (int i = 0; i < 8; ++i) { acc[i][0] = 0ull; acc[i][1] = 0ull; }

    for (int k0 = 0; k0 < K; k0 += 16) {
        float4 a0 = *(const float4*)(arow + k0 + akc);
        float4 a1 = *(const float4*)(arow + k0 + akc + 4);
        float4 bb = *(const float4*)(bptr + (long)k0 * N);

        *(float2*)&As2[akc + 0][r2] = make_float2(a0.x, a0.x);
        *(float2*)&As2[akc + 1][r2] = make_float2(a0.y, a0.y);
        *(float2*)&As2[akc + 2][r2] = make_float2(a0.z, a0.z);
        *(float2*)&As2[akc + 3][r2] = make_float2(a0.w, a0.w);
        *(float2*)&As2[akc + 4][r2] = make_float2(a1.x, a1.x);
        *(float2*)&As2[akc + 5][r2] = make_float2(a1.y, a1.y);
        *(float2*)&As2[akc + 6][r2] = make_float2(a1.z, a1.z);
        *(float2*)&As2[akc + 7][r2] = make_float2(a1.w, a1.w);
        *(float4*)&Bs[bkr][bc] = bb;
        __syncthreads();

#pragma unroll
        for (int kk = 0; kk < 16; ++kk) {
            ulonglong2 b01 = *(const ulonglong2*)&Bs[kk][tx * 4];     // 2 packed cols
            ulonglong2 a01 = *(const ulonglong2*)&As2[kk][ty * 16];   // dup rows 0,1
            ulonglong2 a23 = *(const ulonglong2*)&As2[kk][ty * 16 + 4];
            ulonglong2 a45 = *(const ulonglong2*)&As2[kk][ty * 16 + 8];
            ulonglong2 a67 = *(const ulonglong2*)&As2[kk][ty * 16 + 12];
            unsigned long long ad[8] = {a01.x, a01.y, a23.x, a23.y,
                                        a45.x, a45.y, a67.x, a67.y};
#pragma unroll
            for (int i = 0; i < 8; ++i) {
                FMA2(acc[i][0], ad[i], b01.x, acc[i][0]);
                FMA2(acc[i][1], ad[i], b01.y, acc[i][1]);
            }
        }
        __syncthreads();
    }

    float4 bia = *(const float4*)(bias + col0 + tx * 4);
#pragma unroll
    for (int i = 0; i < 8; ++i) {
        long m = row0 + ty * 8 + i;
        float2 f01 = u2f2(acc[i][0]);
        float2 f23 = u2f2(acc[i][1]);
        float4 v;
        v.x = f01.x + bia.x;
        v.y = f01.y + bia.y;
        v.z = f23.x + bia.z;
        v.w = f23.y + bia.w;
        *(float4*)(g_xg + m * G3 + col0 + tx * 4) = v;
    }
}

// ---------------- grid barrier ----------------
__device__ __forceinline__ void grid_barrier_arrive_wait(unsigned target, unsigned nb)
{
    if (atomicAdd(&g_bar_count, 1u) == nb - 1u) {
        g_bar_count = 0u;
        __threadfence();
        atomicAdd(&g_bar_gen, 1u);
    } else {
        while (*((volatile unsigned*)&g_bar_gen) != target) { }
    }
}

// ---------------- persistent GRU recurrence ----------------
// 128 CTAs x 256 threads. CTA (bgrp, hcgrp): batch rows [bgrp*32,+32),
// hidden cols [hcgrp*8,+8). FFMA2 inner product, packed over gate cols.
__global__ void __launch_bounds__(256, 1) gru_rec_kernel(
    const float* __restrict__ Wh, const float* __restrict__ bhn,
    int write_y, float* __restrict__ cout)
{
    const int NB = 32, NG = 24;
    extern __shared__ __align__(16) float sh[];
    float* ws  = sh;                 // [512][24]   49152 B (16B-aligned rows)
    float* hs  = ws + 512 * NG;      // [512][36]   73728 B (pad 36 -> STS.128 ok)
    float* red = hs + 512 * 36;      // [8][32][26] 26624 B (even stride -> STS.64)
    float* xgs = red + 8 * 32 * 26;  // [32][25]     2560 B

    int tid  = threadIdx.x;
    int warp = tid >> 5, lane = tid & 31;
    int bgrp = blockIdx.x & 1;
    int hc0  = (blockIdx.x >> 1) * 8;
    int b0   = bgrp * NB;

    // load W_h slice into SMEM (once)
    for (int f = tid; f < 512 * NG; f += 256) {
        int k = f / NG, j = f - k * NG;
        int gc = (j >> 3) * HID + hc0 + (j & 7);
        ws[f] = Wh[(long)k * G3 + gc];
    }

    unsigned lgen = 0;
    if (tid == 0) lgen = *((volatile unsigned*)&g_bar_gen);

    int eci = tid & 7;        // hidden col within slice
    int eb  = tid >> 3;       // local batch row 0..31
    int ehc = hc0 + eci;

    for (int t = 0; t < TSEQ; ++t) {
        int cur = t & 1, nxt = cur ^ 1;

        // stage xg tile [32 b][24 gate cols]
        if (tid < 96) {
            int b = tid & 31, grp = tid >> 5;   // grp 0..2 = r,z,n
            const float* p = g_xg + ((long)t * NBATCH + b0 + b) * G3 + grp * HID + hc0;
            float4 v0 = ((const float4*)p)[0];
            float4 v1 = ((const float4*)p)[1];
            float* q = xgs + b * 25 + grp * 8;
            q[0] = v0.x; q[1] = v0.y; q[2] = v0.z; q[3] = v0.w;
            q[4] = v1.x; q[5] = v1.y; q[6] = v1.z; q[7] = v1.w;
        }

        // stage h (k-major global -> SMEM [k][36]); t==0: zeros
        if (t == 0) {
            for (int f = tid; f < 512 * 36; f += 256) hs[f] = 0.f;
        } else {
#pragma unroll
            for (int it = 0; it < 16; ++it) {
                int f4 = tid + it * 256;        // 0..4095
                int k = f4 >> 3, bq = f4 & 7;
                float4 v = __ldcg((const float4*)&g_h[cur][k * NBATCH + b0 + bq * 4]);
                *(float4*)(hs + k * 36 + bq * 4) = v;
            }
        }
        __syncthreads();

        // partial GEMM: warp w covers k in [w*64, w*64+64)
        unsigned long long acc[12];
#pragma unroll
        for (int j = 0; j < 12; ++j) acc[j] = 0ull;
        int kbase = warp << 6;
#pragma unroll 4
        for (int kk = 0; kk < 64; ++kk) {
            int k = kbase + kk;
            float hv = hs[k * 36 + lane];
            unsigned long long hd;
            asm("mov.b64 %0, {%1, %1};" : "=l"(hd) : "r"(__float_as_int(hv)));
            const ulonglong2* wp = (const ulonglong2*)(ws + k * NG);
            ulonglong2 w0 = wp[0], w1 = wp[1], w2 = wp[2];
            FMA2(acc[0],  hd, w0.x, acc[0]);
            FMA2(acc[1],  hd, w0.y, acc[1]);
            FMA2(acc[2],  hd, w1.x, acc[2]);
            FMA2(acc[3],  hd, w1.y, acc[3]);
            FMA2(acc[4],  hd, w2.x, acc[4]);
            FMA2(acc[5],  hd, w2.y, acc[5]);
            ulonglong2 w3 = wp[3], w4 = wp[4], w5 = wp[5];
            FMA2(acc[6],  hd, w3.x, acc[6]);
            FMA2(acc[7],  hd, w3.y, acc[7]);
            FMA2(acc[8],  hd, w4.x, acc[8]);
            FMA2(acc[9],  hd, w4.y, acc[9]);
            FMA2(acc[10], hd, w5.x, acc[10]);
            FMA2(acc[11], hd, w5.y, acc[11]);
        }
        {
            unsigned long long* rp =
                (unsigned long long*)(red + (warp * NB + lane) * 26);
#pragma unroll
            for (int j = 0; j < 12; ++j) rp[j] = acc[j];
        }
        __syncthreads();

        // reduce 8 warps + gate math; thread -> (eb, eci)
        float hr = 0.f, hz = 0.f, hnv = 0.f;
#pragma unroll
        for (int w = 0; w < 8; ++w) {
            const float* pr = red + (w * NB + eb) * 26;
            hr  += pr[eci];
            hz  += pr[8 + eci];
            hnv += pr[16 + eci];
        }
        float xr = xgs[eb * 25 + eci];
        float xz = xgs[eb * 25 + 8 + eci];
        float xn = xgs[eb * 25 + 16 + eci];
        float hprev = hs[ehc * 36 + eb];

        float rg = 1.f / (1.f + __expf(-(xr + hr)));
        float zg = 1.f / (1.f + __expf(-(xz + hz)));
        float ng = tanhf(xn + rg * (hnv + bhn[ehc]));
        float hnew = (1.f - zg) * ng + zg * hprev;

        g_h[nxt][ehc * NBATCH + b0 + eb] = hnew;
        if (write_y)
            g_y0[((long)t * NBATCH + b0 + eb) * HID + ehc] = tanhf(hnew);
        if (t == TSEQ - 1)
            cout[(b0 + eb) * HID + ehc] = hnew;

        __threadfence();
        __syncthreads();
        if (tid == 0) { lgen += 1u; grid_barrier_arrive_wait(lgen, 128u); }
        __syncthreads();
    }
}

// ---------------- dense head: out = tanh(tanh(c1) @ W_out + b_out) ----------------
__global__ void __launch_bounds__(512) dense_kernel(
    const float* __restrict__ Wout, const float* __restrict__ bout,
    float* __restrict__ out)
{
    __shared__ float tsh[HID];
    int b = blockIdx.x;
    int j = threadIdx.x;
    tsh[j] = tanhf(g_h[0][j * NBATCH + b]);   // final h of layer 1 (k-major)
    __syncthreads();
    float s = bout[j];
#pragma unroll 8
    for (int k = 0; k < HID; ++k)
        s = fmaf(tsh[k], Wout[(long)k * 512 + j], s);
    out[b * 512 + j] = tanhf(s);
}

// ---------------- launch ----------------
extern "C" void kernel_launch(void* const* d_in, const int* in_sizes, int n_in,
                              void* d_out, int out_size)
{
    const float* x     = (const float*)d_in[0];
    const float* W_i0  = (const float*)d_in[1];
    const float* b_i0  = (const float*)d_in[2];
    const float* W_h0  = (const float*)d_in[3];
    const float* b_hn0 = (const float*)d_in[4];
    const float* W_i1  = (const float*)d_in[5];
    const float* b_i1  = (const float*)d_in[6];
    const float* W_h1  = (const float*)d_in[7];
    const float* b_hn1 = (const float*)d_in[8];
    const float* W_out = (const float*)d_in[9];
    const float* b_out = (const float*)d_in[10];

    float* out = (float*)d_out;
    float* c0  = out + 64 * 512;
    float* c1  = out + 2 * 64 * 512;

    size_t rec_smem = (size_t)(512 * 24 + 512 * 36 + 8 * 32 * 26 + 32 * 25) * sizeof(float);
    cudaFuncSetAttribute(gru_rec_kernel,
                         cudaFuncAttributeMaxDynamicSharedMemorySize, (int)rec_smem);

    dim3 pgrid(G3 / 64, MROWS / 128);

    // layer 0
    proj_kernel<<<pgrid, 256>>>(x, W_i0, b_i0, INFEAT, (long)1024 * 256, (long)256);
    gru_rec_kernel<<<128, 256, rec_smem>>>(W_h0, b_hn0, 1, c0);
    // layer 1
    proj_kernel<<<pgrid, 256>>>(nullptr, W_i1, b_i1, HID, (long)512, (long)64 * 512);
    gru_rec_kernel<<<128, 256, rec_smem>>>(W_h1, b_hn1, 0, c1);
    // head
    dense_kernel<<<64, 512>>>(W_out, b_out, out);
}